// round 13
// baseline (speedup 1.0000x reference)
#include <cuda_runtime.h>
#include <cuda_bf16.h>
#include <cuda_fp16.h>
#include <cstdint>

#define NN   50000
#define EE   800000
#define INC  512
#define HID  256
#define OUTC 64
#define PHOPS 10

// ================= scratch (static device globals; no allocation) =================
__device__ float  g_h0[(size_t)NN * HID];     // relu(x@W1+b1)
__device__ __half g_hA[(size_t)NN * OUTC];    // ping (fp16 storage, fp32 accumulation)
__device__ __half g_hB[(size_t)NN * OUTC];    // pong
__device__ float  g_hidden[(size_t)NN * OUTC];
__device__ int    g_counts[NN];
__device__ int    g_fill[NN];
__device__ int    g_colptr[NN + 1];
__device__ int2   g_edge[EE];                 // (src, w as float bits)
__device__ float  g_dinv[NN];
__device__ int    g_is64;
// W1 as fp16 mma-fragments: e = (((nb*4+nc)*16+ch)*2+ks)*4+nt  (1024 entries)
__device__ uint2 g_Wfrag[1024 * 32];
// W2 bf16 hi/lo fragments: e = ((ch*2+ks)*8 + n8)*2 + pr (256 entries)
__device__ uint2 g_W2frag[256 * 32];

__device__ __forceinline__ uint32_t smem_u32(const void* p) {
    uint32_t a;
    asm("{ .reg .u64 t; cvta.to.shared.u64 t, %1; cvt.u32.u64 %0, t; }" : "=r"(a) : "l"(p));
    return a;
}
__device__ __forceinline__ uint32_t pack_bf2(float x, float y) {
    __nv_bfloat162 h = __floats2bfloat162_rn(x, y);
    return *(uint32_t*)&h;
}
__device__ __forceinline__ uint32_t pack_hf2(float x, float y) {
    __half2 h = __floats2half2_rn(x, y);
    return *(uint32_t*)&h;
}
#define CP_ASYNC16(dst, src) \
    asm volatile("cp.async.cg.shared.global [%0], [%1], 16;" :: "r"(dst), "l"(src))
#define CP_COMMIT() asm volatile("cp.async.commit_group;" ::: "memory")
#define CP_WAIT(n)  asm volatile("cp.async.wait_group %0;" :: "n"(n) : "memory")

// ================= dtype detection =================
__global__ void k_detect(const void* __restrict__ ei) {
    if (blockIdx.x == 0 && threadIdx.x == 0) {
        const long long* e64 = (const long long*)ei;
        int ok = 1;
#pragma unroll
        for (int i = 0; i < 16; i++) {
            long long v = e64[i];
            if (v < 0 || v >= NN) ok = 0;
        }
        g_is64 = ok;
    }
}

__device__ __forceinline__ void load_edge(const void* __restrict__ ei, int i, int& r, int& c) {
    if (g_is64) {
        r = (int)((const long long*)ei)[i];
        c = (int)((const long long*)ei)[EE + i];
    } else {
        r = ((const int*)ei)[i];
        c = ((const int*)ei)[EE + i];
    }
}

// ================= preprocessing =================
__global__ void k_zero() {
    int i = blockIdx.x * blockDim.x + threadIdx.x;
    if (i < NN) { g_counts[i] = 0; g_fill[i] = 0; }
}

__global__ void k_hist(const void* __restrict__ ei) {
    int i = blockIdx.x * blockDim.x + threadIdx.x;
    if (i < EE) {
        int r, c;
        load_edge(ei, i, r, c);
        if ((unsigned)c < NN) atomicAdd(&g_counts[c], 1);
    }
}

__global__ void k_dinv() {
    int i = blockIdx.x * blockDim.x + threadIdx.x;
    if (i < NN) g_dinv[i] = rsqrtf((float)(g_counts[i] + 1)); // +1 self loop
}

// warp-shuffle exclusive scan of g_counts -> g_colptr (1 block of 1024)
__global__ void k_scan() {
    __shared__ int wsum[32];
    __shared__ int chunk_base;
    int tid = threadIdx.x;
    int lane = tid & 31, wid = tid >> 5;
    if (tid == 0) chunk_base = 0;
    __syncthreads();
    for (int base = 0; base < NN; base += 1024) {
        int i = base + tid;
        int v = (i < NN) ? g_counts[i] : 0;
        int incl = v;
#pragma unroll
        for (int o = 1; o < 32; o <<= 1) {
            int t = __shfl_up_sync(0xffffffffu, incl, o);
            if (lane >= o) incl += t;
        }
        if (lane == 31) wsum[wid] = incl;
        __syncthreads();
        if (wid == 0) {
            int s = wsum[lane];
            int si = s;
#pragma unroll
            for (int o = 1; o < 32; o <<= 1) {
                int t = __shfl_up_sync(0xffffffffu, si, o);
                if (lane >= o) si += t;
            }
            wsum[lane] = si - s;
        }
        __syncthreads();
        int excl = chunk_base + wsum[wid] + incl - v;
        if (i < NN) g_colptr[i] = excl;
        __syncthreads();
        if (tid == 1023) chunk_base = excl + v;
        __syncthreads();
    }
    if (tid == 0) g_colptr[NN] = chunk_base;
}

__global__ void k_scatter(const void* __restrict__ ei) {
    int i = blockIdx.x * blockDim.x + threadIdx.x;
    if (i < EE) {
        int r, c;
        load_edge(ei, i, r, c);
        if ((unsigned)r >= NN || (unsigned)c >= NN) return;
        int pos = g_colptr[c] + atomicAdd(&g_fill[c], 1);
        if ((unsigned)pos < EE) {
            float w = g_dinv[r] * g_dinv[c];
            g_edge[pos] = make_int2(r, __float_as_int(w));
        }
    }
}

// ================= W1 -> fp16 mma fragments (single precision level) =================
__global__ void k_wprep(const float* __restrict__ W1) {
    int t = blockIdx.x * blockDim.x + threadIdx.x;
    if (t >= 1024 * 32) return;
    int lane = t & 31;
    int e = t >> 5;
    int nt = e & 3;
    int ks = (e >> 2) & 1;
    int ch = (e >> 3) & 15;
    int nc = (e >> 7) & 3;
    int nb = (e >> 9) & 1;
    int n  = nb * 128 + nc * 32 + nt * 8 + (lane >> 2);
    int k0 = ch * 32 + ks * 16 + (lane & 3) * 2;
    float w00 = W1[(size_t)k0 * HID + n];
    float w01 = W1[(size_t)(k0 + 1) * HID + n];
    float w10 = W1[(size_t)(k0 + 8) * HID + n];
    float w11 = W1[(size_t)(k0 + 9) * HID + n];
    uint2 out;
    out.x = pack_hf2(w00, w01);
    out.y = pack_hf2(w10, w11);
    g_Wfrag[e * 32 + lane] = out;
}

// ================= W2 -> bf16 hi/lo mma fragments =================
__global__ void k_w2prep(const float* __restrict__ W2) {
    int t = blockIdx.x * blockDim.x + threadIdx.x;
    if (t >= 256 * 32) return;
    int lane = t & 31;
    int e = t >> 5;
    int pr = e & 1;
    int n8 = (e >> 1) & 7;
    int ks = (e >> 4) & 1;
    int ch = e >> 5;
    int n  = n8 * 8 + (lane >> 2);
    int k0 = ch * 32 + ks * 16 + (lane & 3) * 2;
    float w00 = W2[(size_t)k0 * OUTC + n];
    float w01 = W2[(size_t)(k0 + 1) * OUTC + n];
    float w10 = W2[(size_t)(k0 + 8) * OUTC + n];
    float w11 = W2[(size_t)(k0 + 9) * OUTC + n];
    uint2 out;
    if (pr == 0) {
        out.x = pack_bf2(w00, w01);
        out.y = pack_bf2(w10, w11);
    } else {
        out.x = pack_bf2(w00 - __bfloat162float(__float2bfloat16(w00)),
                         w01 - __bfloat162float(__float2bfloat16(w01)));
        out.y = pack_bf2(w10 - __bfloat162float(__float2bfloat16(w10)),
                         w11 - __bfloat162float(__float2bfloat16(w11)));
    }
    g_W2frag[e * 32 + lane] = out;
}

// ================= mma helpers =================
__device__ __forceinline__ void mma16816bf(float* d, const uint32_t* a, const uint2 b) {
    asm volatile(
        "mma.sync.aligned.m16n8k16.row.col.f32.bf16.bf16.f32 "
        "{%0,%1,%2,%3}, {%4,%5,%6,%7}, {%8,%9}, {%0,%1,%2,%3};"
        : "+f"(d[0]), "+f"(d[1]), "+f"(d[2]), "+f"(d[3])
        : "r"(a[0]), "r"(a[1]), "r"(a[2]), "r"(a[3]), "r"(b.x), "r"(b.y));
}
__device__ __forceinline__ void mma16816hf(float* d, const uint32_t* a, const uint2 b) {
    asm volatile(
        "mma.sync.aligned.m16n8k16.row.col.f32.f16.f16.f32 "
        "{%0,%1,%2,%3}, {%4,%5,%6,%7}, {%8,%9}, {%0,%1,%2,%3};"
        : "+f"(d[0]), "+f"(d[1]), "+f"(d[2]), "+f"(d[3])
        : "r"(a[0]), "r"(a[1]), "r"(a[2]), "r"(a[3]), "r"(b.x), "r"(b.y));
}
#define LDSM4(r, addr) \
    asm volatile("ldmatrix.sync.aligned.m8n8.x4.shared.b16 {%0,%1,%2,%3}, [%4];" \
                 : "=r"((r)[0]), "=r"((r)[1]), "=r"((r)[2]), "=r"((r)[3]) : "r"(addr))

// ================= GEMM1: fp16 hi/lo A (exact) x fp16 W1, 2-pass =================
#define G1_SMEM (32768 + 10240 + 10240)

__global__ void __launch_bounds__(256) k_gemm1_mma(const float* __restrict__ X,
                                                   const float* __restrict__ b1) {
    extern __shared__ __align__(16) char smraw[];
    float*    Xs  = (float*)smraw;                    // [2][4096]
    uint32_t* AsH = (uint32_t*)(smraw + 32768);       // [128*20] fp16 hi
    uint32_t* AsL = (uint32_t*)(smraw + 43008);       // [128*20] fp16 lo

    int tid  = threadIdx.x;
    int wid  = tid >> 5, lane = tid & 31;
    int wm0  = (wid >> 2) * 64;
    int nc   = wid & 3;
    int m0   = blockIdx.x * 128;
    int nb   = blockIdx.y;

    float acc[4][4][4];
#pragma unroll
    for (int i = 0; i < 4; i++)
#pragma unroll
        for (int j = 0; j < 4; j++)
#pragma unroll
            for (int q = 0; q < 4; q++) acc[i][j][q] = 0.f;

    uint32_t asmH = smem_u32(AsH), asmL = smem_u32(AsL);
    uint32_t xs_b = smem_u32(Xs);
    uint32_t lrow = (uint32_t)(lane & 15) * 80u + (uint32_t)(lane >> 4) * 16u;

    int srow = tid >> 3, sseg = tid & 7;
    bool valid[4];
    const float* src0[4];
#pragma unroll
    for (int it = 0; it < 4; it++) {
        int row = srow + it * 32;
        int m = m0 + row;
        valid[it] = (m < NN);
        src0[it] = &X[(size_t)(valid[it] ? m : 0) * INC + sseg * 4];
        if (!valid[it]) {
            *(float4*)&Xs[0 * 4096 + row * 32 + sseg * 4] = make_float4(0.f, 0.f, 0.f, 0.f);
            *(float4*)&Xs[1 * 4096 + row * 32 + sseg * 4] = make_float4(0.f, 0.f, 0.f, 0.f);
        }
    }

#pragma unroll
    for (int it = 0; it < 4; it++)
        if (valid[it]) {
            uint32_t dst = xs_b + (uint32_t)((srow + it * 32) * 32 + sseg * 4) * 4u;
            CP_ASYNC16(dst, src0[it]);
        }
    CP_COMMIT();

    for (int ch = 0; ch < 16; ch++) {
        int buf = ch & 1;
        if (ch < 15) {
#pragma unroll
            for (int it = 0; it < 4; it++)
                if (valid[it]) {
                    uint32_t dst = xs_b + (uint32_t)(((ch + 1) & 1) * 4096 +
                                                     (srow + it * 32) * 32 + sseg * 4) * 4u;
                    CP_ASYNC16(dst, src0[it] + (ch + 1) * 32);
                }
            CP_COMMIT();
            CP_WAIT(1);
        } else {
            CP_WAIT(0);
        }
        __syncthreads();
#pragma unroll
        for (int it = 0; it < 4; it++) {
            int row = srow + it * 32;
            float4 v = *(float4*)&Xs[buf * 4096 + row * 32 + sseg * 4];
            int o = row * 20 + sseg * 2;
            float hx = __half2float(__float2half_rn(v.x));
            float hy = __half2float(__float2half_rn(v.y));
            float hz = __half2float(__float2half_rn(v.z));
            float hw = __half2float(__float2half_rn(v.w));
            AsH[o]     = pack_hf2(v.x, v.y);
            AsH[o + 1] = pack_hf2(v.z, v.w);
            AsL[o]     = pack_hf2(v.x - hx, v.y - hy);
            AsL[o + 1] = pack_hf2(v.z - hz, v.w - hw);
        }
        __syncthreads();
#pragma unroll
        for (int ks = 0; ks < 2; ks++) {
            uint32_t aH[4][4], aL[4][4];
#pragma unroll
            for (int mt = 0; mt < 4; mt++) {
                uint32_t off = (uint32_t)(wm0 + mt * 16) * 80u + (uint32_t)ks * 32u + lrow;
                LDSM4(aH[mt], asmH + off);
                LDSM4(aL[mt], asmL + off);
            }
            int base = (((nb * 4 + nc) * 16 + ch) * 2 + ks) * 4;
            uint2 bF[4];
#pragma unroll
            for (int nt = 0; nt < 4; nt++)
                bF[nt] = g_Wfrag[(size_t)(base + nt) * 32 + lane];
#pragma unroll
            for (int mt = 0; mt < 4; mt++)
#pragma unroll
                for (int nt = 0; nt < 4; nt++) mma16816hf(acc[mt][nt], aH[mt], bF[nt]);
#pragma unroll
            for (int mt = 0; mt < 4; mt++)
#pragma unroll
                for (int nt = 0; nt < 4; nt++) mma16816hf(acc[mt][nt], aL[mt], bF[nt]);
        }
    }

#pragma unroll
    for (int mt = 0; mt < 4; mt++) {
        int r0 = m0 + wm0 + mt * 16 + (lane >> 2);
#pragma unroll
        for (int nt = 0; nt < 4; nt++) {
            int gcol = nb * 128 + nc * 32 + nt * 8 + (lane & 3) * 2;
            float bi0 = __ldg(&b1[gcol]), bi1 = __ldg(&b1[gcol + 1]);
            if (r0 < NN) {
                float2 v;
                v.x = fmaxf(acc[mt][nt][0] + bi0, 0.f);
                v.y = fmaxf(acc[mt][nt][1] + bi1, 0.f);
                *(float2*)&g_h0[(size_t)r0 * HID + gcol] = v;
            }
            int r1 = r0 + 8;
            if (r1 < NN) {
                float2 v;
                v.x = fmaxf(acc[mt][nt][2] + bi0, 0.f);
                v.y = fmaxf(acc[mt][nt][3] + bi1, 0.f);
                *(float2*)&g_h0[(size_t)r1 * HID + gcol] = v;
            }
        }
    }
}

// ================= GEMM2 via mma.sync; emits fp16 hA + fp32 hidden =================
__global__ void __launch_bounds__(256) k_gemm2_mma(const float* __restrict__ b2,
                                                   const float* __restrict__ coes) {
    __shared__ __align__(16) uint32_t HsH[128 * 20];
    __shared__ __align__(16) uint32_t HsL[128 * 20];
    int tid  = threadIdx.x;
    int wid  = tid >> 5, lane = tid & 31;
    int wm0  = (wid >> 2) * 64;
    int nc   = wid & 3;
    int m0   = blockIdx.x * 128;

    float acc[4][2][4];
#pragma unroll
    for (int i = 0; i < 4; i++)
#pragma unroll
        for (int j = 0; j < 2; j++)
#pragma unroll
            for (int q = 0; q < 4; q++) acc[i][j][q] = 0.f;

    uint32_t asmH = smem_u32(HsH), asmL = smem_u32(HsL);
    uint32_t lrow = (uint32_t)(lane & 15) * 80u + (uint32_t)(lane >> 4) * 16u;
    int srow = tid >> 3, sseg = tid & 7;

    for (int ch = 0; ch < 8; ch++) {
        __syncthreads();
#pragma unroll
        for (int it = 0; it < 4; it++) {
            int row = srow + it * 32;
            int m = m0 + row;
            float4 v = make_float4(0.f, 0.f, 0.f, 0.f);
            if (m < NN) v = *(const float4*)&g_h0[(size_t)m * HID + ch * 32 + sseg * 4];
            int o = row * 20 + sseg * 2;
            HsH[o]     = pack_bf2(v.x, v.y);
            HsH[o + 1] = pack_bf2(v.z, v.w);
            HsL[o]     = pack_bf2(v.x - __bfloat162float(__float2bfloat16(v.x)),
                                  v.y - __bfloat162float(__float2bfloat16(v.y)));
            HsL[o + 1] = pack_bf2(v.z - __bfloat162float(__float2bfloat16(v.z)),
                                  v.w - __bfloat162float(__float2bfloat16(v.w)));
        }
        __syncthreads();
#pragma unroll
        for (int ks = 0; ks < 2; ks++) {
            uint32_t aH[4][4], aL[4][4];
#pragma unroll
            for (int mt = 0; mt < 4; mt++) {
                uint32_t off = (uint32_t)(wm0 + mt * 16) * 80u + (uint32_t)ks * 32u + lrow;
                LDSM4(aH[mt], asmH + off);
                LDSM4(aL[mt], asmL + off);
            }
            uint2 bH[2], bL[2];
#pragma unroll
            for (int nt = 0; nt < 2; nt++) {
                int e0 = ((ch * 2 + ks) * 8 + nc * 2 + nt) * 2;
                bH[nt] = g_W2frag[(size_t)(e0 + 0) * 32 + lane];
                bL[nt] = g_W2frag[(size_t)(e0 + 1) * 32 + lane];
            }
#pragma unroll
            for (int mt = 0; mt < 4; mt++)
#pragma unroll
                for (int nt = 0; nt < 2; nt++) {
                    mma16816bf(acc[mt][nt], aH[mt], bH[nt]);
                    mma16816bf(acc[mt][nt], aL[mt], bH[nt]);
                    mma16816bf(acc[mt][nt], aH[mt], bL[nt]);
                }
        }
    }

    float c0 = __ldg(&coes[0]);
#pragma unroll
    for (int mt = 0; mt < 4; mt++) {
        int r0 = m0 + wm0 + mt * 16 + (lane >> 2);
#pragma unroll
        for (int nt = 0; nt < 2; nt++) {
            int gcol = nc * 16 + nt * 8 + (lane & 3) * 2;
            float bi0 = __ldg(&b2[gcol]), bi1 = __ldg(&b2[gcol + 1]);
#pragma unroll
            for (int h = 0; h < 2; h++) {
                int r = r0 + h * 8;
                if (r < NN) {
                    float vx = acc[mt][nt][h * 2 + 0] + bi0;
                    float vy = acc[mt][nt][h * 2 + 1] + bi1;
                    size_t o = (size_t)r * OUTC + gcol;
                    *(__half2*)&g_hA[o]    = __floats2half2_rn(vx, vy);
                    *(float2*)&g_hidden[o] = make_float2(c0 * vx, c0 * vy);
                }
            }
        }
    }
}

// ===== SpMM hop: warp/node, packed edges, x4-unrolled gather, fp32 accum + hidden RMW =====
__global__ void k_spmm(int parity, const float* __restrict__ coes, int p) {
    int gid  = blockIdx.x * blockDim.x + threadIdx.x;
    int node = gid >> 5;
    int lane = gid & 31;
    if (node >= NN) return;
    const __half2* __restrict__ hin  = (const __half2*)(parity ? g_hB : g_hA);
    __half2* __restrict__       hout = (__half2*)(parity ? g_hA : g_hB);

    int beg = g_colptr[node], end = g_colptr[node + 1];
    float a0 = 0.f, a1 = 0.f, b0 = 0.f, b1 = 0.f;
    float c0 = 0.f, c1 = 0.f, d0 = 0.f, d1 = 0.f;
    int e = beg;
    for (; e + 3 < end; e += 4) {
        int2 e0 = g_edge[e];
        int2 e1 = g_edge[e + 1];
        int2 e2 = g_edge[e + 2];
        int2 e3 = g_edge[e + 3];
        __half2 v0 = hin[(size_t)e0.x * 32 + lane];
        __half2 v1 = hin[(size_t)e1.x * 32 + lane];
        __half2 v2 = hin[(size_t)e2.x * 32 + lane];
        __half2 v3 = hin[(size_t)e3.x * 32 + lane];
        float w0 = __int_as_float(e0.y), w1 = __int_as_float(e1.y);
        float w2 = __int_as_float(e2.y), w3 = __int_as_float(e3.y);
        float2 f0 = __half22float2(v0), f1 = __half22float2(v1);
        float2 f2 = __half22float2(v2), f3 = __half22float2(v3);
        a0 = fmaf(w0, f0.x, a0); a1 = fmaf(w0, f0.y, a1);
        b0 = fmaf(w1, f1.x, b0); b1 = fmaf(w1, f1.y, b1);
        c0 = fmaf(w2, f2.x, c0); c1 = fmaf(w2, f2.y, c1);
        d0 = fmaf(w3, f3.x, d0); d1 = fmaf(w3, f3.y, d1);
    }
    for (; e < end; e++) {
        int2 ed = g_edge[e];
        __half2 v = hin[(size_t)ed.x * 32 + lane];
        float w = __int_as_float(ed.y);
        float2 f = __half22float2(v);
        a0 = fmaf(w, f.x, a0); a1 = fmaf(w, f.y, a1);
    }
    // self loop
    {
        float d = g_dinv[node];
        float wd = d * d;
        __half2 v = hin[(size_t)node * 32 + lane];
        float2 f = __half22float2(v);
        b0 = fmaf(wd, f.x, b0); b1 = fmaf(wd, f.y, b1);
    }
    float sx = (a0 + b0) + (c0 + d0);
    float sy = (a1 + b1) + (c1 + d1);

    hout[(size_t)node * 32 + lane] = __floats2half2_rn(sx, sy);
    float c = coes[p];
    float2* hd = (float2*)(g_hidden + (size_t)node * OUTC);
    float2 t = hd[lane];
    t.x = fmaf(c, sx, t.x);
    t.y = fmaf(c, sy, t.y);
    hd[lane] = t;
}

// ================= log_softmax over 64 feats (pair-per-lane layout) =================
__global__ void k_lsm(float* __restrict__ out) {
    int gid  = blockIdx.x * blockDim.x + threadIdx.x;
    int node = gid >> 5;
    int lane = gid & 31;
    if (node >= NN) return;
    size_t o = (size_t)node * OUTC;
    float2 v = ((const float2*)(g_hidden + o))[lane];
    float m = fmaxf(v.x, v.y);
#pragma unroll
    for (int off = 16; off; off >>= 1) m = fmaxf(m, __shfl_xor_sync(0xffffffffu, m, off));
    float s = expf(v.x - m) + expf(v.y - m);
#pragma unroll
    for (int off = 16; off; off >>= 1) s += __shfl_xor_sync(0xffffffffu, s, off);
    float l = m + logf(s);
    ((float2*)(out + o))[lane] = make_float2(v.x - l, v.y - l);
}

// ================= launch =================
extern "C" void kernel_launch(void* const* d_in, const int* in_sizes, int n_in,
                              void* d_out, int out_size) {
    const float* x    = (const float*)d_in[0];
    const void*  ei   = d_in[1];
    const float* W1   = (const float*)d_in[2];
    const float* b1   = (const float*)d_in[3];
    const float* W2   = (const float*)d_in[4];
    const float* b2   = (const float*)d_in[5];
    const float* coes = (const float*)d_in[6];
    (void)in_sizes; (void)n_in; (void)out_size;

    cudaFuncSetAttribute(k_gemm1_mma, cudaFuncAttributeMaxDynamicSharedMemorySize, G1_SMEM);

    // Fork-join: graph preprocessing on a side stream, MLP chain on the origin stream.
    cudaStream_t sp;
    cudaEvent_t e1, e2;
    cudaStreamCreateWithFlags(&sp, cudaStreamNonBlocking);
    cudaEventCreateWithFlags(&e1, cudaEventDisableTiming);
    cudaEventCreateWithFlags(&e2, cudaEventDisableTiming);

    cudaEventRecord(e1, 0);
    cudaStreamWaitEvent(sp, e1, 0);

    // --- side stream: edge preprocessing ---
    k_detect<<<1, 32, 0, sp>>>(ei);
    k_zero<<<(NN + 255) / 256, 256, 0, sp>>>();
    k_hist<<<(EE + 255) / 256, 256, 0, sp>>>(ei);
    k_dinv<<<(NN + 255) / 256, 256, 0, sp>>>();
    k_scan<<<1, 1024, 0, sp>>>();
    k_scatter<<<(EE + 255) / 256, 256, 0, sp>>>(ei);
    cudaEventRecord(e2, sp);

    // --- origin stream: MLP ---
    k_wprep<<<(1024 * 32 + 255) / 256, 256>>>(W1);
    k_w2prep<<<(256 * 32 + 255) / 256, 256>>>(W2);
    dim3 g1((NN + 127) / 128, 2);
    k_gemm1_mma<<<g1, 256, G1_SMEM>>>(x, b1);
    k_gemm2_mma<<<(NN + 127) / 128, 256>>>(b2, coes);

    // join: SpMM needs CSR (side) + hA/hidden (origin)
    cudaStreamWaitEvent(0, e2, 0);

    int warpsGrid = (NN * 32 + 255) / 256;
    for (int hp = 0; hp < PHOPS; hp++)
        k_spmm<<<warpsGrid, 256>>>(hp & 1, coes, hp + 1);

    k_lsm<<<warpsGrid, 256>>>((float*)d_out);

    cudaEventDestroy(e1);
    cudaEventDestroy(e2);
    cudaStreamDestroy(sp);
}

// round 14
// speedup vs baseline: 1.2477x; 1.2477x over previous
#include <cuda_runtime.h>
#include <cuda_bf16.h>
#include <cuda_fp16.h>
#include <cstdint>

#define NN   50000
#define EE   800000
#define INC  512
#define HID  256
#define OUTC 64
#define PHOPS 10

// ================= scratch (static device globals; no allocation) =================
__device__ float  g_h0[(size_t)NN * HID];     // relu(x@W1+b1)
__device__ __half g_hA[(size_t)NN * OUTC];    // ping (fp16 storage, fp32 accumulation)
__device__ __half g_hB[(size_t)NN * OUTC];    // pong
__device__ float  g_hidden[(size_t)NN * OUTC];
__device__ int    g_counts[NN];
__device__ int    g_fill[NN];
__device__ int    g_colptr[NN + 1];
__device__ int2   g_edge[EE];                 // (src, w as float bits)
__device__ float  g_dinv[NN];
__device__ int    g_is64;
// W1 as fp16 mma-fragments: e = (((nb*4+nc)*16+ch)*2+ks)*4+nt  (1024 entries)
__device__ uint2 g_Wfrag[1024 * 32];
// W2 bf16 hi/lo fragments: e = ((ch*2+ks)*8 + n8)*2 + pr (256 entries)
__device__ uint2 g_W2frag[256 * 32];

__device__ __forceinline__ uint32_t smem_u32(const void* p) {
    uint32_t a;
    asm("{ .reg .u64 t; cvta.to.shared.u64 t, %1; cvt.u32.u64 %0, t; }" : "=r"(a) : "l"(p));
    return a;
}
__device__ __forceinline__ uint32_t pack_bf2(float x, float y) {
    __nv_bfloat162 h = __floats2bfloat162_rn(x, y);
    return *(uint32_t*)&h;
}
__device__ __forceinline__ uint32_t pack_hf2(float x, float y) {
    __half2 h = __floats2half2_rn(x, y);
    return *(uint32_t*)&h;
}
#define CP_ASYNC16(dst, src) \
    asm volatile("cp.async.cg.shared.global [%0], [%1], 16;" :: "r"(dst), "l"(src))
#define CP_COMMIT() asm volatile("cp.async.commit_group;" ::: "memory")
#define CP_WAIT(n)  asm volatile("cp.async.wait_group %0;" :: "n"(n) : "memory")

// ================= dtype detection =================
__global__ void k_detect(const void* __restrict__ ei) {
    if (blockIdx.x == 0 && threadIdx.x == 0) {
        const long long* e64 = (const long long*)ei;
        int ok = 1;
#pragma unroll
        for (int i = 0; i < 16; i++) {
            long long v = e64[i];
            if (v < 0 || v >= NN) ok = 0;
        }
        g_is64 = ok;
    }
}

__device__ __forceinline__ void load_edge(const void* __restrict__ ei, int i, int& r, int& c) {
    if (g_is64) {
        r = (int)((const long long*)ei)[i];
        c = (int)((const long long*)ei)[EE + i];
    } else {
        r = ((const int*)ei)[i];
        c = ((const int*)ei)[EE + i];
    }
}

// ================= preprocessing =================
__global__ void k_zero() {
    int i = blockIdx.x * blockDim.x + threadIdx.x;
    if (i < NN) { g_counts[i] = 0; g_fill[i] = 0; }
}

__global__ void k_hist(const void* __restrict__ ei) {
    int i = blockIdx.x * blockDim.x + threadIdx.x;
    if (i < EE) {
        int r, c;
        load_edge(ei, i, r, c);
        if ((unsigned)c < NN) atomicAdd(&g_counts[c], 1);
    }
}

__global__ void k_dinv() {
    int i = blockIdx.x * blockDim.x + threadIdx.x;
    if (i < NN) g_dinv[i] = rsqrtf((float)(g_counts[i] + 1)); // +1 self loop
}

// warp-shuffle exclusive scan of g_counts -> g_colptr (1 block of 1024)
__global__ void k_scan() {
    __shared__ int wsum[32];
    __shared__ int chunk_base;
    int tid = threadIdx.x;
    int lane = tid & 31, wid = tid >> 5;
    if (tid == 0) chunk_base = 0;
    __syncthreads();
    for (int base = 0; base < NN; base += 1024) {
        int i = base + tid;
        int v = (i < NN) ? g_counts[i] : 0;
        int incl = v;
#pragma unroll
        for (int o = 1; o < 32; o <<= 1) {
            int t = __shfl_up_sync(0xffffffffu, incl, o);
            if (lane >= o) incl += t;
        }
        if (lane == 31) wsum[wid] = incl;
        __syncthreads();
        if (wid == 0) {
            int s = wsum[lane];
            int si = s;
#pragma unroll
            for (int o = 1; o < 32; o <<= 1) {
                int t = __shfl_up_sync(0xffffffffu, si, o);
                if (lane >= o) si += t;
            }
            wsum[lane] = si - s;
        }
        __syncthreads();
        int excl = chunk_base + wsum[wid] + incl - v;
        if (i < NN) g_colptr[i] = excl;
        __syncthreads();
        if (tid == 1023) chunk_base = excl + v;
        __syncthreads();
    }
    if (tid == 0) g_colptr[NN] = chunk_base;
}

__global__ void k_scatter(const void* __restrict__ ei) {
    int i = blockIdx.x * blockDim.x + threadIdx.x;
    if (i < EE) {
        int r, c;
        load_edge(ei, i, r, c);
        if ((unsigned)r >= NN || (unsigned)c >= NN) return;
        int pos = g_colptr[c] + atomicAdd(&g_fill[c], 1);
        if ((unsigned)pos < EE) {
            float w = g_dinv[r] * g_dinv[c];
            g_edge[pos] = make_int2(r, __float_as_int(w));
        }
    }
}

// ================= W1 -> fp16 mma fragments (single precision level) =================
__global__ void k_wprep(const float* __restrict__ W1) {
    int t = blockIdx.x * blockDim.x + threadIdx.x;
    if (t >= 1024 * 32) return;
    int lane = t & 31;
    int e = t >> 5;
    int nt = e & 3;
    int ks = (e >> 2) & 1;
    int ch = (e >> 3) & 15;
    int nc = (e >> 7) & 3;
    int nb = (e >> 9) & 1;
    int n  = nb * 128 + nc * 32 + nt * 8 + (lane >> 2);
    int k0 = ch * 32 + ks * 16 + (lane & 3) * 2;
    float w00 = W1[(size_t)k0 * HID + n];
    float w01 = W1[(size_t)(k0 + 1) * HID + n];
    float w10 = W1[(size_t)(k0 + 8) * HID + n];
    float w11 = W1[(size_t)(k0 + 9) * HID + n];
    uint2 out;
    out.x = pack_hf2(w00, w01);
    out.y = pack_hf2(w10, w11);
    g_Wfrag[e * 32 + lane] = out;
}

// ================= W2 -> bf16 hi/lo mma fragments =================
__global__ void k_w2prep(const float* __restrict__ W2) {
    int t = blockIdx.x * blockDim.x + threadIdx.x;
    if (t >= 256 * 32) return;
    int lane = t & 31;
    int e = t >> 5;
    int pr = e & 1;
    int n8 = (e >> 1) & 7;
    int ks = (e >> 4) & 1;
    int ch = e >> 5;
    int n  = n8 * 8 + (lane >> 2);
    int k0 = ch * 32 + ks * 16 + (lane & 3) * 2;
    float w00 = W2[(size_t)k0 * OUTC + n];
    float w01 = W2[(size_t)(k0 + 1) * OUTC + n];
    float w10 = W2[(size_t)(k0 + 8) * OUTC + n];
    float w11 = W2[(size_t)(k0 + 9) * OUTC + n];
    uint2 out;
    if (pr == 0) {
        out.x = pack_bf2(w00, w01);
        out.y = pack_bf2(w10, w11);
    } else {
        out.x = pack_bf2(w00 - __bfloat162float(__float2bfloat16(w00)),
                         w01 - __bfloat162float(__float2bfloat16(w01)));
        out.y = pack_bf2(w10 - __bfloat162float(__float2bfloat16(w10)),
                         w11 - __bfloat162float(__float2bfloat16(w11)));
    }
    g_W2frag[e * 32 + lane] = out;
}

// ================= mma helpers =================
__device__ __forceinline__ void mma16816bf(float* d, const uint32_t* a, const uint2 b) {
    asm volatile(
        "mma.sync.aligned.m16n8k16.row.col.f32.bf16.bf16.f32 "
        "{%0,%1,%2,%3}, {%4,%5,%6,%7}, {%8,%9}, {%0,%1,%2,%3};"
        : "+f"(d[0]), "+f"(d[1]), "+f"(d[2]), "+f"(d[3])
        : "r"(a[0]), "r"(a[1]), "r"(a[2]), "r"(a[3]), "r"(b.x), "r"(b.y));
}
__device__ __forceinline__ void mma16816hf(float* d, const uint32_t* a, const uint2 b) {
    asm volatile(
        "mma.sync.aligned.m16n8k16.row.col.f32.f16.f16.f32 "
        "{%0,%1,%2,%3}, {%4,%5,%6,%7}, {%8,%9}, {%0,%1,%2,%3};"
        : "+f"(d[0]), "+f"(d[1]), "+f"(d[2]), "+f"(d[3])
        : "r"(a[0]), "r"(a[1]), "r"(a[2]), "r"(a[3]), "r"(b.x), "r"(b.y));
}
#define LDSM4(r, addr) \
    asm volatile("ldmatrix.sync.aligned.m8n8.x4.shared.b16 {%0,%1,%2,%3}, [%4];" \
                 : "=r"((r)[0]), "=r"((r)[1]), "=r"((r)[2]), "=r"((r)[3]) : "r"(addr))

// ================= GEMM1: fp16 hi/lo A (exact) x fp16 W1, 2-pass =================
#define G1_SMEM (32768 + 10240 + 10240)

__global__ void __launch_bounds__(256) k_gemm1_mma(const float* __restrict__ X,
                                                   const float* __restrict__ b1) {
    extern __shared__ __align__(16) char smraw[];
    float*    Xs  = (float*)smraw;                    // [2][4096]
    uint32_t* AsH = (uint32_t*)(smraw + 32768);       // [128*20] fp16 hi
    uint32_t* AsL = (uint32_t*)(smraw + 43008);       // [128*20] fp16 lo

    int tid  = threadIdx.x;
    int wid  = tid >> 5, lane = tid & 31;
    int wm0  = (wid >> 2) * 64;
    int nc   = wid & 3;
    int m0   = blockIdx.x * 128;
    int nb   = blockIdx.y;

    float acc[4][4][4];
#pragma unroll
    for (int i = 0; i < 4; i++)
#pragma unroll
        for (int j = 0; j < 4; j++)
#pragma unroll
            for (int q = 0; q < 4; q++) acc[i][j][q] = 0.f;

    uint32_t asmH = smem_u32(AsH), asmL = smem_u32(AsL);
    uint32_t xs_b = smem_u32(Xs);
    uint32_t lrow = (uint32_t)(lane & 15) * 80u + (uint32_t)(lane >> 4) * 16u;

    int srow = tid >> 3, sseg = tid & 7;
    bool valid[4];
    const float* src0[4];
#pragma unroll
    for (int it = 0; it < 4; it++) {
        int row = srow + it * 32;
        int m = m0 + row;
        valid[it] = (m < NN);
        src0[it] = &X[(size_t)(valid[it] ? m : 0) * INC + sseg * 4];
        if (!valid[it]) {
            *(float4*)&Xs[0 * 4096 + row * 32 + sseg * 4] = make_float4(0.f, 0.f, 0.f, 0.f);
            *(float4*)&Xs[1 * 4096 + row * 32 + sseg * 4] = make_float4(0.f, 0.f, 0.f, 0.f);
        }
    }

#pragma unroll
    for (int it = 0; it < 4; it++)
        if (valid[it]) {
            uint32_t dst = xs_b + (uint32_t)((srow + it * 32) * 32 + sseg * 4) * 4u;
            CP_ASYNC16(dst, src0[it]);
        }
    CP_COMMIT();

    for (int ch = 0; ch < 16; ch++) {
        int buf = ch & 1;
        if (ch < 15) {
#pragma unroll
            for (int it = 0; it < 4; it++)
                if (valid[it]) {
                    uint32_t dst = xs_b + (uint32_t)(((ch + 1) & 1) * 4096 +
                                                     (srow + it * 32) * 32 + sseg * 4) * 4u;
                    CP_ASYNC16(dst, src0[it] + (ch + 1) * 32);
                }
            CP_COMMIT();
            CP_WAIT(1);
        } else {
            CP_WAIT(0);
        }
        __syncthreads();
#pragma unroll
        for (int it = 0; it < 4; it++) {
            int row = srow + it * 32;
            float4 v = *(float4*)&Xs[buf * 4096 + row * 32 + sseg * 4];
            int o = row * 20 + sseg * 2;
            float hx = __half2float(__float2half_rn(v.x));
            float hy = __half2float(__float2half_rn(v.y));
            float hz = __half2float(__float2half_rn(v.z));
            float hw = __half2float(__float2half_rn(v.w));
            AsH[o]     = pack_hf2(v.x, v.y);
            AsH[o + 1] = pack_hf2(v.z, v.w);
            AsL[o]     = pack_hf2(v.x - hx, v.y - hy);
            AsL[o + 1] = pack_hf2(v.z - hz, v.w - hw);
        }
        __syncthreads();
#pragma unroll
        for (int ks = 0; ks < 2; ks++) {
            uint32_t aH[4][4], aL[4][4];
#pragma unroll
            for (int mt = 0; mt < 4; mt++) {
                uint32_t off = (uint32_t)(wm0 + mt * 16) * 80u + (uint32_t)ks * 32u + lrow;
                LDSM4(aH[mt], asmH + off);
                LDSM4(aL[mt], asmL + off);
            }
            int base = (((nb * 4 + nc) * 16 + ch) * 2 + ks) * 4;
            uint2 bF[4];
#pragma unroll
            for (int nt = 0; nt < 4; nt++)
                bF[nt] = g_Wfrag[(size_t)(base + nt) * 32 + lane];
#pragma unroll
            for (int mt = 0; mt < 4; mt++)
#pragma unroll
                for (int nt = 0; nt < 4; nt++) mma16816hf(acc[mt][nt], aH[mt], bF[nt]);
#pragma unroll
            for (int mt = 0; mt < 4; mt++)
#pragma unroll
                for (int nt = 0; nt < 4; nt++) mma16816hf(acc[mt][nt], aL[mt], bF[nt]);
        }
    }

#pragma unroll
    for (int mt = 0; mt < 4; mt++) {
        int r0 = m0 + wm0 + mt * 16 + (lane >> 2);
#pragma unroll
        for (int nt = 0; nt < 4; nt++) {
            int gcol = nb * 128 + nc * 32 + nt * 8 + (lane & 3) * 2;
            float bi0 = __ldg(&b1[gcol]), bi1 = __ldg(&b1[gcol + 1]);
            if (r0 < NN) {
                float2 v;
                v.x = fmaxf(acc[mt][nt][0] + bi0, 0.f);
                v.y = fmaxf(acc[mt][nt][1] + bi1, 0.f);
                *(float2*)&g_h0[(size_t)r0 * HID + gcol] = v;
            }
            int r1 = r0 + 8;
            if (r1 < NN) {
                float2 v;
                v.x = fmaxf(acc[mt][nt][2] + bi0, 0.f);
                v.y = fmaxf(acc[mt][nt][3] + bi1, 0.f);
                *(float2*)&g_h0[(size_t)r1 * HID + gcol] = v;
            }
        }
    }
}

// ================= GEMM2 via mma.sync; emits fp16 hA + fp32 hidden =================
__global__ void __launch_bounds__(256) k_gemm2_mma(const float* __restrict__ b2,
                                                   const float* __restrict__ coes) {
    __shared__ __align__(16) uint32_t HsH[128 * 20];
    __shared__ __align__(16) uint32_t HsL[128 * 20];
    int tid  = threadIdx.x;
    int wid  = tid >> 5, lane = tid & 31;
    int wm0  = (wid >> 2) * 64;
    int nc   = wid & 3;
    int m0   = blockIdx.x * 128;

    float acc[4][2][4];
#pragma unroll
    for (int i = 0; i < 4; i++)
#pragma unroll
        for (int j = 0; j < 2; j++)
#pragma unroll
            for (int q = 0; q < 4; q++) acc[i][j][q] = 0.f;

    uint32_t asmH = smem_u32(HsH), asmL = smem_u32(HsL);
    uint32_t lrow = (uint32_t)(lane & 15) * 80u + (uint32_t)(lane >> 4) * 16u;
    int srow = tid >> 3, sseg = tid & 7;

    for (int ch = 0; ch < 8; ch++) {
        __syncthreads();
#pragma unroll
        for (int it = 0; it < 4; it++) {
            int row = srow + it * 32;
            int m = m0 + row;
            float4 v = make_float4(0.f, 0.f, 0.f, 0.f);
            if (m < NN) v = *(const float4*)&g_h0[(size_t)m * HID + ch * 32 + sseg * 4];
            int o = row * 20 + sseg * 2;
            HsH[o]     = pack_bf2(v.x, v.y);
            HsH[o + 1] = pack_bf2(v.z, v.w);
            HsL[o]     = pack_bf2(v.x - __bfloat162float(__float2bfloat16(v.x)),
                                  v.y - __bfloat162float(__float2bfloat16(v.y)));
            HsL[o + 1] = pack_bf2(v.z - __bfloat162float(__float2bfloat16(v.z)),
                                  v.w - __bfloat162float(__float2bfloat16(v.w)));
        }
        __syncthreads();
#pragma unroll
        for (int ks = 0; ks < 2; ks++) {
            uint32_t aH[4][4], aL[4][4];
#pragma unroll
            for (int mt = 0; mt < 4; mt++) {
                uint32_t off = (uint32_t)(wm0 + mt * 16) * 80u + (uint32_t)ks * 32u + lrow;
                LDSM4(aH[mt], asmH + off);
                LDSM4(aL[mt], asmL + off);
            }
            uint2 bH[2], bL[2];
#pragma unroll
            for (int nt = 0; nt < 2; nt++) {
                int e0 = ((ch * 2 + ks) * 8 + nc * 2 + nt) * 2;
                bH[nt] = g_W2frag[(size_t)(e0 + 0) * 32 + lane];
                bL[nt] = g_W2frag[(size_t)(e0 + 1) * 32 + lane];
            }
#pragma unroll
            for (int mt = 0; mt < 4; mt++)
#pragma unroll
                for (int nt = 0; nt < 2; nt++) {
                    mma16816bf(acc[mt][nt], aH[mt], bH[nt]);
                    mma16816bf(acc[mt][nt], aL[mt], bH[nt]);
                    mma16816bf(acc[mt][nt], aH[mt], bL[nt]);
                }
        }
    }

    float c0 = __ldg(&coes[0]);
#pragma unroll
    for (int mt = 0; mt < 4; mt++) {
        int r0 = m0 + wm0 + mt * 16 + (lane >> 2);
#pragma unroll
        for (int nt = 0; nt < 2; nt++) {
            int gcol = nc * 16 + nt * 8 + (lane & 3) * 2;
            float bi0 = __ldg(&b2[gcol]), bi1 = __ldg(&b2[gcol + 1]);
#pragma unroll
            for (int h = 0; h < 2; h++) {
                int r = r0 + h * 8;
                if (r < NN) {
                    float vx = acc[mt][nt][h * 2 + 0] + bi0;
                    float vy = acc[mt][nt][h * 2 + 1] + bi1;
                    size_t o = (size_t)r * OUTC + gcol;
                    *(__half2*)&g_hA[o]    = __floats2half2_rn(vx, vy);
                    *(float2*)&g_hidden[o] = make_float2(c0 * vx, c0 * vy);
                }
            }
        }
    }
}

// ===== SpMM hop: warp/node, simple loop (R10 form), packed int2 edges =====
__global__ void k_spmm(int parity, const float* __restrict__ coes, int p) {
    int gid  = blockIdx.x * blockDim.x + threadIdx.x;
    int node = gid >> 5;
    int lane = gid & 31;
    if (node >= NN) return;
    const __half2* __restrict__ hin  = (const __half2*)(parity ? g_hB : g_hA);
    __half2* __restrict__       hout = (__half2*)(parity ? g_hA : g_hB);

    int beg = g_colptr[node], end = g_colptr[node + 1];
    float a0 = 0.f, a1 = 0.f;
    for (int e = beg; e < end; e++) {
        int2 ed = g_edge[e];
        __half2 v = hin[(size_t)ed.x * 32 + lane];
        float w = __int_as_float(ed.y);
        float2 f = __half22float2(v);
        a0 = fmaf(w, f.x, a0);
        a1 = fmaf(w, f.y, a1);
    }
    // self loop
    {
        float d = g_dinv[node];
        float wd = d * d;
        __half2 v = hin[(size_t)node * 32 + lane];
        float2 f = __half22float2(v);
        a0 = fmaf(wd, f.x, a0);
        a1 = fmaf(wd, f.y, a1);
    }

    hout[(size_t)node * 32 + lane] = __floats2half2_rn(a0, a1);
    float c = coes[p];
    float2* hd = (float2*)(g_hidden + (size_t)node * OUTC);
    float2 t = hd[lane];
    t.x = fmaf(c, a0, t.x);
    t.y = fmaf(c, a1, t.y);
    hd[lane] = t;
}

// ================= log_softmax over 64 feats (pair-per-lane layout) =================
__global__ void k_lsm(float* __restrict__ out) {
    int gid  = blockIdx.x * blockDim.x + threadIdx.x;
    int node = gid >> 5;
    int lane = gid & 31;
    if (node >= NN) return;
    size_t o = (size_t)node * OUTC;
    float2 v = ((const float2*)(g_hidden + o))[lane];
    float m = fmaxf(v.x, v.y);
#pragma unroll
    for (int off = 16; off; off >>= 1) m = fmaxf(m, __shfl_xor_sync(0xffffffffu, m, off));
    float s = expf(v.x - m) + expf(v.y - m);
#pragma unroll
    for (int off = 16; off; off >>= 1) s += __shfl_xor_sync(0xffffffffu, s, off);
    float l = m + logf(s);
    ((float2*)(out + o))[lane] = make_float2(v.x - l, v.y - l);
}

// ================= launch =================
extern "C" void kernel_launch(void* const* d_in, const int* in_sizes, int n_in,
                              void* d_out, int out_size) {
    const float* x    = (const float*)d_in[0];
    const void*  ei   = d_in[1];
    const float* W1   = (const float*)d_in[2];
    const float* b1   = (const float*)d_in[3];
    const float* W2   = (const float*)d_in[4];
    const float* b2   = (const float*)d_in[5];
    const float* coes = (const float*)d_in[6];
    (void)in_sizes; (void)n_in; (void)out_size;

    cudaFuncSetAttribute(k_gemm1_mma, cudaFuncAttributeMaxDynamicSharedMemorySize, G1_SMEM);

    // Fork-join: graph preprocessing on a side stream, MLP chain on the origin stream.
    cudaStream_t sp;
    cudaEvent_t e1, e2;
    cudaStreamCreateWithFlags(&sp, cudaStreamNonBlocking);
    cudaEventCreateWithFlags(&e1, cudaEventDisableTiming);
    cudaEventCreateWithFlags(&e2, cudaEventDisableTiming);

    cudaEventRecord(e1, 0);
    cudaStreamWaitEvent(sp, e1, 0);

    // --- side stream: edge preprocessing ---
    k_detect<<<1, 32, 0, sp>>>(ei);
    k_zero<<<(NN + 255) / 256, 256, 0, sp>>>();
    k_hist<<<(EE + 255) / 256, 256, 0, sp>>>(ei);
    k_dinv<<<(NN + 255) / 256, 256, 0, sp>>>();
    k_scan<<<1, 1024, 0, sp>>>();
    k_scatter<<<(EE + 255) / 256, 256, 0, sp>>>(ei);
    cudaEventRecord(e2, sp);

    // --- origin stream: MLP ---
    k_wprep<<<(1024 * 32 + 255) / 256, 256>>>(W1);
    k_w2prep<<<(256 * 32 + 255) / 256, 256>>>(W2);
    dim3 g1((NN + 127) / 128, 2);
    k_gemm1_mma<<<g1, 256, G1_SMEM>>>(x, b1);
    k_gemm2_mma<<<(NN + 127) / 128, 256>>>(b2, coes);

    // join: SpMM needs CSR (side) + hA/hidden (origin)
    cudaStreamWaitEvent(0, e2, 0);

    int warpsGrid = (NN * 32 + 255) / 256;
    for (int hp = 0; hp < PHOPS; hp++)
        k_spmm<<<warpsGrid, 256>>>(hp & 1, coes, hp + 1);

    k_lsm<<<warpsGrid, 256>>>((float*)d_out);

    cudaEventDestroy(e1);
    cudaEventDestroy(e2);
    cudaStreamDestroy(sp);
}

// round 16
// speedup vs baseline: 1.2604x; 1.0102x over previous
#include <cuda_runtime.h>
#include <cuda_bf16.h>
#include <cuda_fp16.h>
#include <cstdint>

#define NN   50000
#define EE   800000
#define INC  512
#define HID  256
#define OUTC 64
#define PHOPS 10

// ================= scratch (static device globals; no allocation) =================
__device__ float  g_h0[(size_t)NN * HID];     // relu(x@W1+b1)
__device__ __half g_hA[(size_t)NN * OUTC];    // ping (fp16 storage, fp32 accumulation)
__device__ __half g_hB[(size_t)NN * OUTC];    // pong
__device__ float  g_hidden[(size_t)NN * OUTC];
__device__ int    g_counts[NN];
__device__ int    g_fill[NN];
__device__ int    g_colptr[NN + 1];
__device__ int2   g_edge[EE];                 // (src, w as float bits)
__device__ float  g_dinv[NN];
__device__ int    g_is64;
// W1 as fp16 mma-fragments: e = (((nb*4+nc)*16+ch)*2+ks)*4+nt  (1024 entries)
__device__ uint2 g_Wfrag[1024 * 32];
// W2 fp16 fragments: e = (ch*2+ks)*8 + n8   (128 entries)
__device__ uint2 g_W2frag[128 * 32];

__device__ __forceinline__ uint32_t smem_u32(const void* p) {
    uint32_t a;
    asm("{ .reg .u64 t; cvta.to.shared.u64 t, %1; cvt.u32.u64 %0, t; }" : "=r"(a) : "l"(p));
    return a;
}
__device__ __forceinline__ uint32_t pack_hf2(float x, float y) {
    __half2 h = __floats2half2_rn(x, y);
    return *(uint32_t*)&h;
}
#define CP_ASYNC16(dst, src) \
    asm volatile("cp.async.cg.shared.global [%0], [%1], 16;" :: "r"(dst), "l"(src))
#define CP_COMMIT() asm volatile("cp.async.commit_group;" ::: "memory")
#define CP_WAIT(n)  asm volatile("cp.async.wait_group %0;" :: "n"(n) : "memory")

// ================= dtype detection =================
__global__ void k_detect(const void* __restrict__ ei) {
    if (blockIdx.x == 0 && threadIdx.x == 0) {
        const long long* e64 = (const long long*)ei;
        int ok = 1;
#pragma unroll
        for (int i = 0; i < 16; i++) {
            long long v = e64[i];
            if (v < 0 || v >= NN) ok = 0;
        }
        g_is64 = ok;
    }
}

__device__ __forceinline__ void load_edge(const void* __restrict__ ei, int i, int& r, int& c) {
    if (g_is64) {
        r = (int)((const long long*)ei)[i];
        c = (int)((const long long*)ei)[EE + i];
    } else {
        r = ((const int*)ei)[i];
        c = ((const int*)ei)[EE + i];
    }
}

// ================= preprocessing =================
__global__ void k_zero() {
    int i = blockIdx.x * blockDim.x + threadIdx.x;
    if (i < NN) { g_counts[i] = 0; g_fill[i] = 0; }
}

__global__ void k_hist(const void* __restrict__ ei) {
    int i = blockIdx.x * blockDim.x + threadIdx.x;
    if (i < EE) {
        int r, c;
        load_edge(ei, i, r, c);
        if ((unsigned)c < NN) atomicAdd(&g_counts[c], 1);
    }
}

__global__ void k_dinv() {
    int i = blockIdx.x * blockDim.x + threadIdx.x;
    if (i < NN) g_dinv[i] = rsqrtf((float)(g_counts[i] + 1)); // +1 self loop
}

// warp-shuffle exclusive scan of g_counts -> g_colptr (1 block of 1024)
__global__ void k_scan() {
    __shared__ int wsum[32];
    __shared__ int chunk_base;
    int tid = threadIdx.x;
    int lane = tid & 31, wid = tid >> 5;
    if (tid == 0) chunk_base = 0;
    __syncthreads();
    for (int base = 0; base < NN; base += 1024) {
        int i = base + tid;
        int v = (i < NN) ? g_counts[i] : 0;
        int incl = v;
#pragma unroll
        for (int o = 1; o < 32; o <<= 1) {
            int t = __shfl_up_sync(0xffffffffu, incl, o);
            if (lane >= o) incl += t;
        }
        if (lane == 31) wsum[wid] = incl;
        __syncthreads();
        if (wid == 0) {
            int s = wsum[lane];
            int si = s;
#pragma unroll
            for (int o = 1; o < 32; o <<= 1) {
                int t = __shfl_up_sync(0xffffffffu, si, o);
                if (lane >= o) si += t;
            }
            wsum[lane] = si - s;
        }
        __syncthreads();
        int excl = chunk_base + wsum[wid] + incl - v;
        if (i < NN) g_colptr[i] = excl;
        __syncthreads();
        if (tid == 1023) chunk_base = excl + v;
        __syncthreads();
    }
    if (tid == 0) g_colptr[NN] = chunk_base;
}

__global__ void k_scatter(const void* __restrict__ ei) {
    int i = blockIdx.x * blockDim.x + threadIdx.x;
    if (i < EE) {
        int r, c;
        load_edge(ei, i, r, c);
        if ((unsigned)r >= NN || (unsigned)c >= NN) return;
        int pos = g_colptr[c] + atomicAdd(&g_fill[c], 1);
        if ((unsigned)pos < EE) {
            float w = g_dinv[r] * g_dinv[c];
            g_edge[pos] = make_int2(r, __float_as_int(w));
        }
    }
}

// ================= W1 -> fp16 mma fragments =================
__global__ void k_wprep(const float* __restrict__ W1) {
    int t = blockIdx.x * blockDim.x + threadIdx.x;
    if (t >= 1024 * 32) return;
    int lane = t & 31;
    int e = t >> 5;
    int nt = e & 3;
    int ks = (e >> 2) & 1;
    int ch = (e >> 3) & 15;
    int nc = (e >> 7) & 3;
    int nb = (e >> 9) & 1;
    int n  = nb * 128 + nc * 32 + nt * 8 + (lane >> 2);
    int k0 = ch * 32 + ks * 16 + (lane & 3) * 2;
    float w00 = W1[(size_t)k0 * HID + n];
    float w01 = W1[(size_t)(k0 + 1) * HID + n];
    float w10 = W1[(size_t)(k0 + 8) * HID + n];
    float w11 = W1[(size_t)(k0 + 9) * HID + n];
    uint2 out;
    out.x = pack_hf2(w00, w01);
    out.y = pack_hf2(w10, w11);
    g_Wfrag[e * 32 + lane] = out;
}

// ================= W2 -> fp16 mma fragments =================
__global__ void k_w2prep(const float* __restrict__ W2) {
    int t = blockIdx.x * blockDim.x + threadIdx.x;
    if (t >= 128 * 32) return;
    int lane = t & 31;
    int e = t >> 5;
    int n8 = e & 7;
    int ks = (e >> 3) & 1;
    int ch = e >> 4;
    int n  = n8 * 8 + (lane >> 2);
    int k0 = ch * 32 + ks * 16 + (lane & 3) * 2;
    float w00 = W2[(size_t)k0 * OUTC + n];
    float w01 = W2[(size_t)(k0 + 1) * OUTC + n];
    float w10 = W2[(size_t)(k0 + 8) * OUTC + n];
    float w11 = W2[(size_t)(k0 + 9) * OUTC + n];
    uint2 out;
    out.x = pack_hf2(w00, w01);
    out.y = pack_hf2(w10, w11);
    g_W2frag[e * 32 + lane] = out;
}

// ================= mma helper =================
__device__ __forceinline__ void mma16816hf(float* d, const uint32_t* a, const uint2 b) {
    asm volatile(
        "mma.sync.aligned.m16n8k16.row.col.f32.f16.f16.f32 "
        "{%0,%1,%2,%3}, {%4,%5,%6,%7}, {%8,%9}, {%0,%1,%2,%3};"
        : "+f"(d[0]), "+f"(d[1]), "+f"(d[2]), "+f"(d[3])
        : "r"(a[0]), "r"(a[1]), "r"(a[2]), "r"(a[3]), "r"(b.x), "r"(b.y));
}
#define LDSM4(r, addr) \
    asm volatile("ldmatrix.sync.aligned.m8n8.x4.shared.b16 {%0,%1,%2,%3}, [%4];" \
                 : "=r"((r)[0]), "=r"((r)[1]), "=r"((r)[2]), "=r"((r)[3]) : "r"(addr))

// ================= GEMM1: fp16 A x fp16 W1, single pass =================
// SMEM: Xs raw fp32 [2][4096] (32KB) + AsH [128*20] (10KB) = 43008.
#define G1_SMEM (32768 + 10240)

__global__ void __launch_bounds__(256) k_gemm1_mma(const float* __restrict__ X,
                                                   const float* __restrict__ b1) {
    extern __shared__ __align__(16) char smraw[];
    float*    Xs  = (float*)smraw;                    // [2][4096]
    uint32_t* AsH = (uint32_t*)(smraw + 32768);       // [128*20] fp16

    int tid  = threadIdx.x;
    int wid  = tid >> 5, lane = tid & 31;
    int wm0  = (wid >> 2) * 64;
    int nc   = wid & 3;
    int m0   = blockIdx.x * 128;
    int nb   = blockIdx.y;

    float acc[4][4][4];
#pragma unroll
    for (int i = 0; i < 4; i++)
#pragma unroll
        for (int j = 0; j < 4; j++)
#pragma unroll
            for (int q = 0; q < 4; q++) acc[i][j][q] = 0.f;

    uint32_t asmH = smem_u32(AsH);
    uint32_t xs_b = smem_u32(Xs);
    uint32_t lrow = (uint32_t)(lane & 15) * 80u + (uint32_t)(lane >> 4) * 16u;

    int srow = tid >> 3, sseg = tid & 7;
    bool valid[4];
    const float* src0[4];
#pragma unroll
    for (int it = 0; it < 4; it++) {
        int row = srow + it * 32;
        int m = m0 + row;
        valid[it] = (m < NN);
        src0[it] = &X[(size_t)(valid[it] ? m : 0) * INC + sseg * 4];
        if (!valid[it]) {
            *(float4*)&Xs[0 * 4096 + row * 32 + sseg * 4] = make_float4(0.f, 0.f, 0.f, 0.f);
            *(float4*)&Xs[1 * 4096 + row * 32 + sseg * 4] = make_float4(0.f, 0.f, 0.f, 0.f);
        }
    }

#pragma unroll
    for (int it = 0; it < 4; it++)
        if (valid[it]) {
            uint32_t dst = xs_b + (uint32_t)((srow + it * 32) * 32 + sseg * 4) * 4u;
            CP_ASYNC16(dst, src0[it]);
        }
    CP_COMMIT();

    for (int ch = 0; ch < 16; ch++) {
        int buf = ch & 1;
        if (ch < 15) {
#pragma unroll
            for (int it = 0; it < 4; it++)
                if (valid[it]) {
                    uint32_t dst = xs_b + (uint32_t)(((ch + 1) & 1) * 4096 +
                                                     (srow + it * 32) * 32 + sseg * 4) * 4u;
                    CP_ASYNC16(dst, src0[it] + (ch + 1) * 32);
                }
            CP_COMMIT();
            CP_WAIT(1);
        } else {
            CP_WAIT(0);
        }
        __syncthreads();
#pragma unroll
        for (int it = 0; it < 4; it++) {
            int row = srow + it * 32;
            float4 v = *(float4*)&Xs[buf * 4096 + row * 32 + sseg * 4];
            int o = row * 20 + sseg * 2;
            AsH[o]     = pack_hf2(v.x, v.y);
            AsH[o + 1] = pack_hf2(v.z, v.w);
        }
        __syncthreads();
#pragma unroll
        for (int ks = 0; ks < 2; ks++) {
            uint32_t aH[4][4];
#pragma unroll
            for (int mt = 0; mt < 4; mt++) {
                uint32_t off = (uint32_t)(wm0 + mt * 16) * 80u + (uint32_t)ks * 32u + lrow;
                LDSM4(aH[mt], asmH + off);
            }
            int base = (((nb * 4 + nc) * 16 + ch) * 2 + ks) * 4;
            uint2 bF[4];
#pragma unroll
            for (int nt = 0; nt < 4; nt++)
                bF[nt] = g_Wfrag[(size_t)(base + nt) * 32 + lane];
#pragma unroll
            for (int mt = 0; mt < 4; mt++)
#pragma unroll
                for (int nt = 0; nt < 4; nt++) mma16816hf(acc[mt][nt], aH[mt], bF[nt]);
        }
    }

#pragma unroll
    for (int mt = 0; mt < 4; mt++) {
        int r0 = m0 + wm0 + mt * 16 + (lane >> 2);
#pragma unroll
        for (int nt = 0; nt < 4; nt++) {
            int gcol = nb * 128 + nc * 32 + nt * 8 + (lane & 3) * 2;
            float bi0 = __ldg(&b1[gcol]), bi1 = __ldg(&b1[gcol + 1]);
            if (r0 < NN) {
                float2 v;
                v.x = fmaxf(acc[mt][nt][0] + bi0, 0.f);
                v.y = fmaxf(acc[mt][nt][1] + bi1, 0.f);
                *(float2*)&g_h0[(size_t)r0 * HID + gcol] = v;
            }
            int r1 = r0 + 8;
            if (r1 < NN) {
                float2 v;
                v.x = fmaxf(acc[mt][nt][2] + bi0, 0.f);
                v.y = fmaxf(acc[mt][nt][3] + bi1, 0.f);
                *(float2*)&g_h0[(size_t)r1 * HID + gcol] = v;
            }
        }
    }
}

// ========== GEMM2: fp16 hi/lo A (exact) x fp16 W2, 2-pass; emits fp16 hA + fp32 hidden ==========
__global__ void __launch_bounds__(256) k_gemm2_mma(const float* __restrict__ b2,
                                                   const float* __restrict__ coes) {
    __shared__ __align__(16) uint32_t HsH[128 * 20];
    __shared__ __align__(16) uint32_t HsL[128 * 20];
    int tid  = threadIdx.x;
    int wid  = tid >> 5, lane = tid & 31;
    int wm0  = (wid >> 2) * 64;
    int nc   = wid & 3;
    int m0   = blockIdx.x * 128;

    float acc[4][2][4];
#pragma unroll
    for (int i = 0; i < 4; i++)
#pragma unroll
        for (int j = 0; j < 2; j++)
#pragma unroll
            for (int q = 0; q < 4; q++) acc[i][j][q] = 0.f;

    uint32_t asmH = smem_u32(HsH), asmL = smem_u32(HsL);
    uint32_t lrow = (uint32_t)(lane & 15) * 80u + (uint32_t)(lane >> 4) * 16u;
    int srow = tid >> 3, sseg = tid & 7;

    for (int ch = 0; ch < 8; ch++) {
        __syncthreads();
#pragma unroll
        for (int it = 0; it < 4; it++) {
            int row = srow + it * 32;
            int m = m0 + row;
            float4 v = make_float4(0.f, 0.f, 0.f, 0.f);
            if (m < NN) v = *(const float4*)&g_h0[(size_t)m * HID + ch * 32 + sseg * 4];
            int o = row * 20 + sseg * 2;
            float hx = __half2float(__float2half_rn(v.x));
            float hy = __half2float(__float2half_rn(v.y));
            float hz = __half2float(__float2half_rn(v.z));
            float hw = __half2float(__float2half_rn(v.w));
            HsH[o]     = pack_hf2(v.x, v.y);
            HsH[o + 1] = pack_hf2(v.z, v.w);
            HsL[o]     = pack_hf2(v.x - hx, v.y - hy);
            HsL[o + 1] = pack_hf2(v.z - hz, v.w - hw);
        }
        __syncthreads();
#pragma unroll
        for (int ks = 0; ks < 2; ks++) {
            uint32_t aH[4][4], aL[4][4];
#pragma unroll
            for (int mt = 0; mt < 4; mt++) {
                uint32_t off = (uint32_t)(wm0 + mt * 16) * 80u + (uint32_t)ks * 32u + lrow;
                LDSM4(aH[mt], asmH + off);
                LDSM4(aL[mt], asmL + off);
            }
            uint2 bF[2];
#pragma unroll
            for (int nt = 0; nt < 2; nt++) {
                int e0 = (ch * 2 + ks) * 8 + nc * 2 + nt;
                bF[nt] = g_W2frag[(size_t)e0 * 32 + lane];
            }
#pragma unroll
            for (int mt = 0; mt < 4; mt++)
#pragma unroll
                for (int nt = 0; nt < 2; nt++) {
                    mma16816hf(acc[mt][nt], aH[mt], bF[nt]);
                    mma16816hf(acc[mt][nt], aL[mt], bF[nt]);
                }
        }
    }

    float c0 = __ldg(&coes[0]);
#pragma unroll
    for (int mt = 0; mt < 4; mt++) {
        int r0 = m0 + wm0 + mt * 16 + (lane >> 2);
#pragma unroll
        for (int nt = 0; nt < 2; nt++) {
            int gcol = nc * 16 + nt * 8 + (lane & 3) * 2;
            float bi0 = __ldg(&b2[gcol]), bi1 = __ldg(&b2[gcol + 1]);
#pragma unroll
            for (int h = 0; h < 2; h++) {
                int r = r0 + h * 8;
                if (r < NN) {
                    float vx = acc[mt][nt][h * 2 + 0] + bi0;
                    float vy = acc[mt][nt][h * 2 + 1] + bi1;
                    size_t o = (size_t)r * OUTC + gcol;
                    *(__half2*)&g_hA[o]    = __floats2half2_rn(vx, vy);
                    *(float2*)&g_hidden[o] = make_float2(c0 * vx, c0 * vy);
                }
            }
        }
    }
}

// ===== SpMM hop: warp/node, simple loop (R14 form, proven), packed int2 edges =====
__global__ void k_spmm(int parity, const float* __restrict__ coes, int p) {
    int gid  = blockIdx.x * blockDim.x + threadIdx.x;
    int node = gid >> 5;
    int lane = gid & 31;
    if (node >= NN) return;
    const __half2* __restrict__ hin  = (const __half2*)(parity ? g_hB : g_hA);
    __half2* __restrict__       hout = (__half2*)(parity ? g_hA : g_hB);

    int beg = g_colptr[node], end = g_colptr[node + 1];
    float a0 = 0.f, a1 = 0.f;
    for (int e = beg; e < end; e++) {
        int2 ed = g_edge[e];
        __half2 v = hin[(size_t)ed.x * 32 + lane];
        float w = __int_as_float(ed.y);
        float2 f = __half22float2(v);
        a0 = fmaf(w, f.x, a0);
        a1 = fmaf(w, f.y, a1);
    }
    // self loop
    {
        float d = g_dinv[node];
        float wd = d * d;
        __half2 v = hin[(size_t)node * 32 + lane];
        float2 f = __half22float2(v);
        a0 = fmaf(wd, f.x, a0);
        a1 = fmaf(wd, f.y, a1);
    }

    hout[(size_t)node * 32 + lane] = __floats2half2_rn(a0, a1);
    float c = coes[p];
    float2* hd = (float2*)(g_hidden + (size_t)node * OUTC);
    float2 t = hd[lane];
    t.x = fmaf(c, a0, t.x);
    t.y = fmaf(c, a1, t.y);
    hd[lane] = t;
}

// ================= log_softmax over 64 feats (pair-per-lane layout) =================
__global__ void k_lsm(float* __restrict__ out) {
    int gid  = blockIdx.x * blockDim.x + threadIdx.x;
    int node = gid >> 5;
    int lane = gid & 31;
    if (node >= NN) return;
    size_t o = (size_t)node * OUTC;
    float2 v = ((const float2*)(g_hidden + o))[lane];
    float m = fmaxf(v.x, v.y);
#pragma unroll
    for (int off = 16; off; off >>= 1) m = fmaxf(m, __shfl_xor_sync(0xffffffffu, m, off));
    float s = expf(v.x - m) + expf(v.y - m);
#pragma unroll
    for (int off = 16; off; off >>= 1) s += __shfl_xor_sync(0xffffffffu, s, off);
    float l = m + logf(s);
    ((float2*)(out + o))[lane] = make_float2(v.x - l, v.y - l);
}

// ================= launch =================
extern "C" void kernel_launch(void* const* d_in, const int* in_sizes, int n_in,
                              void* d_out, int out_size) {
    const float* x    = (const float*)d_in[0];
    const void*  ei   = d_in[1];
    const float* W1   = (const float*)d_in[2];
    const float* b1   = (const float*)d_in[3];
    const float* W2   = (const float*)d_in[4];
    const float* b2   = (const float*)d_in[5];
    const float* coes = (const float*)d_in[6];
    (void)in_sizes; (void)n_in; (void)out_size;

    cudaFuncSetAttribute(k_gemm1_mma, cudaFuncAttributeMaxDynamicSharedMemorySize, G1_SMEM);

    // Fork-join: graph preprocessing on a side stream, MLP chain on the origin stream.
    cudaStream_t sp;
    cudaEvent_t e1, e2;
    cudaStreamCreateWithFlags(&sp, cudaStreamNonBlocking);
    cudaEventCreateWithFlags(&e1, cudaEventDisableTiming);
    cudaEventCreateWithFlags(&e2, cudaEventDisableTiming);

    cudaEventRecord(e1, 0);
    cudaStreamWaitEvent(sp, e1, 0);

    // --- side stream: edge preprocessing ---
    k_detect<<<1, 32, 0, sp>>>(ei);
    k_zero<<<(NN + 255) / 256, 256, 0, sp>>>();
    k_hist<<<(EE + 255) / 256, 256, 0, sp>>>(ei);
    k_dinv<<<(NN + 255) / 256, 256, 0, sp>>>();
    k_scan<<<1, 1024, 0, sp>>>();
    k_scatter<<<(EE + 255) / 256, 256, 0, sp>>>(ei);
    cudaEventRecord(e2, sp);

    // --- origin stream: MLP ---
    k_wprep<<<(1024 * 32 + 255) / 256, 256>>>(W1);
    k_w2prep<<<(128 * 32 + 255) / 256, 256>>>(W2);
    dim3 g1((NN + 127) / 128, 2);
    k_gemm1_mma<<<g1, 256, G1_SMEM>>>(x, b1);
    k_gemm2_mma<<<(NN + 127) / 128, 256>>>(b2, coes);

    // join: SpMM needs CSR (side) + hA/hidden (origin)
    cudaStreamWaitEvent(0, e2, 0);

    int warpsGrid = (NN * 32 + 255) / 256;
    for (int hp = 0; hp < PHOPS; hp++)
        k_spmm<<<warpsGrid, 256>>>(hp & 1, coes, hp + 1);

    k_lsm<<<warpsGrid, 256>>>((float*)d_out);

    cudaEventDestroy(e1);
    cudaEventDestroy(e2);
    cudaStreamDestroy(sp);
}

// round 17
// speedup vs baseline: 1.2997x; 1.0312x over previous
#include <cuda_runtime.h>
#include <cuda_bf16.h>
#include <cuda_fp16.h>
#include <cstdint>

#define NN   50000
#define EE   800000
#define INC  512
#define HID  256
#define OUTC 64
#define PHOPS 10

// ================= scratch (static device globals; no allocation) =================
__device__ float  g_h0[(size_t)NN * HID];               // relu(x@W1+b1)
__device__ __half g_hops[PHOPS + 1][(size_t)NN * OUTC]; // h_p for p=0..10 (fp16, write-only per hop)
__device__ int    g_counts[NN];
__device__ int    g_fill[NN];
__device__ int    g_colptr[NN + 1];
__device__ int2   g_edge[EE];                           // (src, w as float bits)
__device__ float  g_dinv[NN];
__device__ int    g_is64;
// W1 as fp16 mma-fragments: e = (((nb*4+nc)*16+ch)*2+ks)*4+nt  (1024 entries)
__device__ uint2 g_Wfrag[1024 * 32];
// W2 fp16 fragments: e = (ch*2+ks)*8 + n8   (128 entries)
__device__ uint2 g_W2frag[128 * 32];

__device__ __forceinline__ uint32_t smem_u32(const void* p) {
    uint32_t a;
    asm("{ .reg .u64 t; cvta.to.shared.u64 t, %1; cvt.u32.u64 %0, t; }" : "=r"(a) : "l"(p));
    return a;
}
__device__ __forceinline__ uint32_t pack_hf2(float x, float y) {
    __half2 h = __floats2half2_rn(x, y);
    return *(uint32_t*)&h;
}
#define CP_ASYNC16(dst, src) \
    asm volatile("cp.async.cg.shared.global [%0], [%1], 16;" :: "r"(dst), "l"(src))
#define CP_COMMIT() asm volatile("cp.async.commit_group;" ::: "memory")
#define CP_WAIT(n)  asm volatile("cp.async.wait_group %0;" :: "n"(n) : "memory")

// ================= dtype detection =================
__global__ void k_detect(const void* __restrict__ ei) {
    if (blockIdx.x == 0 && threadIdx.x == 0) {
        const long long* e64 = (const long long*)ei;
        int ok = 1;
#pragma unroll
        for (int i = 0; i < 16; i++) {
            long long v = e64[i];
            if (v < 0 || v >= NN) ok = 0;
        }
        g_is64 = ok;
    }
}

__device__ __forceinline__ void load_edge(const void* __restrict__ ei, int i, int& r, int& c) {
    if (g_is64) {
        r = (int)((const long long*)ei)[i];
        c = (int)((const long long*)ei)[EE + i];
    } else {
        r = ((const int*)ei)[i];
        c = ((const int*)ei)[EE + i];
    }
}

// ================= preprocessing =================
__global__ void k_zero() {
    int i = blockIdx.x * blockDim.x + threadIdx.x;
    if (i < NN) { g_counts[i] = 0; g_fill[i] = 0; }
}

__global__ void k_hist(const void* __restrict__ ei) {
    int i = blockIdx.x * blockDim.x + threadIdx.x;
    if (i < EE) {
        int r, c;
        load_edge(ei, i, r, c);
        if ((unsigned)c < NN) atomicAdd(&g_counts[c], 1);
    }
}

__global__ void k_dinv() {
    int i = blockIdx.x * blockDim.x + threadIdx.x;
    if (i < NN) g_dinv[i] = rsqrtf((float)(g_counts[i] + 1)); // +1 self loop
}

// warp-shuffle exclusive scan of g_counts -> g_colptr (1 block of 1024)
__global__ void k_scan() {
    __shared__ int wsum[32];
    __shared__ int chunk_base;
    int tid = threadIdx.x;
    int lane = tid & 31, wid = tid >> 5;
    if (tid == 0) chunk_base = 0;
    __syncthreads();
    for (int base = 0; base < NN; base += 1024) {
        int i = base + tid;
        int v = (i < NN) ? g_counts[i] : 0;
        int incl = v;
#pragma unroll
        for (int o = 1; o < 32; o <<= 1) {
            int t = __shfl_up_sync(0xffffffffu, incl, o);
            if (lane >= o) incl += t;
        }
        if (lane == 31) wsum[wid] = incl;
        __syncthreads();
        if (wid == 0) {
            int s = wsum[lane];
            int si = s;
#pragma unroll
            for (int o = 1; o < 32; o <<= 1) {
                int t = __shfl_up_sync(0xffffffffu, si, o);
                if (lane >= o) si += t;
            }
            wsum[lane] = si - s;
        }
        __syncthreads();
        int excl = chunk_base + wsum[wid] + incl - v;
        if (i < NN) g_colptr[i] = excl;
        __syncthreads();
        if (tid == 1023) chunk_base = excl + v;
        __syncthreads();
    }
    if (tid == 0) g_colptr[NN] = chunk_base;
}

__global__ void k_scatter(const void* __restrict__ ei) {
    int i = blockIdx.x * blockDim.x + threadIdx.x;
    if (i < EE) {
        int r, c;
        load_edge(ei, i, r, c);
        if ((unsigned)r >= NN || (unsigned)c >= NN) return;
        int pos = g_colptr[c] + atomicAdd(&g_fill[c], 1);
        if ((unsigned)pos < EE) {
            float w = g_dinv[r] * g_dinv[c];
            g_edge[pos] = make_int2(r, __float_as_int(w));
        }
    }
}

// ================= W1 -> fp16 mma fragments =================
__global__ void k_wprep(const float* __restrict__ W1) {
    int t = blockIdx.x * blockDim.x + threadIdx.x;
    if (t >= 1024 * 32) return;
    int lane = t & 31;
    int e = t >> 5;
    int nt = e & 3;
    int ks = (e >> 2) & 1;
    int ch = (e >> 3) & 15;
    int nc = (e >> 7) & 3;
    int nb = (e >> 9) & 1;
    int n  = nb * 128 + nc * 32 + nt * 8 + (lane >> 2);
    int k0 = ch * 32 + ks * 16 + (lane & 3) * 2;
    float w00 = W1[(size_t)k0 * HID + n];
    float w01 = W1[(size_t)(k0 + 1) * HID + n];
    float w10 = W1[(size_t)(k0 + 8) * HID + n];
    float w11 = W1[(size_t)(k0 + 9) * HID + n];
    uint2 out;
    out.x = pack_hf2(w00, w01);
    out.y = pack_hf2(w10, w11);
    g_Wfrag[e * 32 + lane] = out;
}

// ================= W2 -> fp16 mma fragments =================
__global__ void k_w2prep(const float* __restrict__ W2) {
    int t = blockIdx.x * blockDim.x + threadIdx.x;
    if (t >= 128 * 32) return;
    int lane = t & 31;
    int e = t >> 5;
    int n8 = e & 7;
    int ks = (e >> 3) & 1;
    int ch = e >> 4;
    int n  = n8 * 8 + (lane >> 2);
    int k0 = ch * 32 + ks * 16 + (lane & 3) * 2;
    float w00 = W2[(size_t)k0 * OUTC + n];
    float w01 = W2[(size_t)(k0 + 1) * OUTC + n];
    float w10 = W2[(size_t)(k0 + 8) * OUTC + n];
    float w11 = W2[(size_t)(k0 + 9) * OUTC + n];
    uint2 out;
    out.x = pack_hf2(w00, w01);
    out.y = pack_hf2(w10, w11);
    g_W2frag[e * 32 + lane] = out;
}

// ================= mma helper =================
__device__ __forceinline__ void mma16816hf(float* d, const uint32_t* a, const uint2 b) {
    asm volatile(
        "mma.sync.aligned.m16n8k16.row.col.f32.f16.f16.f32 "
        "{%0,%1,%2,%3}, {%4,%5,%6,%7}, {%8,%9}, {%0,%1,%2,%3};"
        : "+f"(d[0]), "+f"(d[1]), "+f"(d[2]), "+f"(d[3])
        : "r"(a[0]), "r"(a[1]), "r"(a[2]), "r"(a[3]), "r"(b.x), "r"(b.y));
}
#define LDSM4(r, addr) \
    asm volatile("ldmatrix.sync.aligned.m8n8.x4.shared.b16 {%0,%1,%2,%3}, [%4];" \
                 : "=r"((r)[0]), "=r"((r)[1]), "=r"((r)[2]), "=r"((r)[3]) : "r"(addr))

// ================= GEMM1: fp16 A x fp16 W1, single pass =================
// SMEM: Xs raw fp32 [2][4096] (32KB) + AsH [128*20] (10KB) = 43008.
#define G1_SMEM (32768 + 10240)

__global__ void __launch_bounds__(256) k_gemm1_mma(const float* __restrict__ X,
                                                   const float* __restrict__ b1) {
    extern __shared__ __align__(16) char smraw[];
    float*    Xs  = (float*)smraw;                    // [2][4096]
    uint32_t* AsH = (uint32_t*)(smraw + 32768);       // [128*20] fp16

    int tid  = threadIdx.x;
    int wid  = tid >> 5, lane = tid & 31;
    int wm0  = (wid >> 2) * 64;
    int nc   = wid & 3;
    int m0   = blockIdx.x * 128;
    int nb   = blockIdx.y;

    float acc[4][4][4];
#pragma unroll
    for (int i = 0; i < 4; i++)
#pragma unroll
        for (int j = 0; j < 4; j++)
#pragma unroll
            for (int q = 0; q < 4; q++) acc[i][j][q] = 0.f;

    uint32_t asmH = smem_u32(AsH);
    uint32_t xs_b = smem_u32(Xs);
    uint32_t lrow = (uint32_t)(lane & 15) * 80u + (uint32_t)(lane >> 4) * 16u;

    int srow = tid >> 3, sseg = tid & 7;
    bool valid[4];
    const float* src0[4];
#pragma unroll
    for (int it = 0; it < 4; it++) {
        int row = srow + it * 32;
        int m = m0 + row;
        valid[it] = (m < NN);
        src0[it] = &X[(size_t)(valid[it] ? m : 0) * INC + sseg * 4];
        if (!valid[it]) {
            *(float4*)&Xs[0 * 4096 + row * 32 + sseg * 4] = make_float4(0.f, 0.f, 0.f, 0.f);
            *(float4*)&Xs[1 * 4096 + row * 32 + sseg * 4] = make_float4(0.f, 0.f, 0.f, 0.f);
        }
    }

#pragma unroll
    for (int it = 0; it < 4; it++)
        if (valid[it]) {
            uint32_t dst = xs_b + (uint32_t)((srow + it * 32) * 32 + sseg * 4) * 4u;
            CP_ASYNC16(dst, src0[it]);
        }
    CP_COMMIT();

    for (int ch = 0; ch < 16; ch++) {
        int buf = ch & 1;
        if (ch < 15) {
#pragma unroll
            for (int it = 0; it < 4; it++)
                if (valid[it]) {
                    uint32_t dst = xs_b + (uint32_t)(((ch + 1) & 1) * 4096 +
                                                     (srow + it * 32) * 32 + sseg * 4) * 4u;
                    CP_ASYNC16(dst, src0[it] + (ch + 1) * 32);
                }
            CP_COMMIT();
            CP_WAIT(1);
        } else {
            CP_WAIT(0);
        }
        __syncthreads();
#pragma unroll
        for (int it = 0; it < 4; it++) {
            int row = srow + it * 32;
            float4 v = *(float4*)&Xs[buf * 4096 + row * 32 + sseg * 4];
            int o = row * 20 + sseg * 2;
            AsH[o]     = pack_hf2(v.x, v.y);
            AsH[o + 1] = pack_hf2(v.z, v.w);
        }
        __syncthreads();
#pragma unroll
        for (int ks = 0; ks < 2; ks++) {
            uint32_t aH[4][4];
#pragma unroll
            for (int mt = 0; mt < 4; mt++) {
                uint32_t off = (uint32_t)(wm0 + mt * 16) * 80u + (uint32_t)ks * 32u + lrow;
                LDSM4(aH[mt], asmH + off);
            }
            int base = (((nb * 4 + nc) * 16 + ch) * 2 + ks) * 4;
            uint2 bF[4];
#pragma unroll
            for (int nt = 0; nt < 4; nt++)
                bF[nt] = g_Wfrag[(size_t)(base + nt) * 32 + lane];
#pragma unroll
            for (int mt = 0; mt < 4; mt++)
#pragma unroll
                for (int nt = 0; nt < 4; nt++) mma16816hf(acc[mt][nt], aH[mt], bF[nt]);
        }
    }

#pragma unroll
    for (int mt = 0; mt < 4; mt++) {
        int r0 = m0 + wm0 + mt * 16 + (lane >> 2);
#pragma unroll
        for (int nt = 0; nt < 4; nt++) {
            int gcol = nb * 128 + nc * 32 + nt * 8 + (lane & 3) * 2;
            float bi0 = __ldg(&b1[gcol]), bi1 = __ldg(&b1[gcol + 1]);
            if (r0 < NN) {
                float2 v;
                v.x = fmaxf(acc[mt][nt][0] + bi0, 0.f);
                v.y = fmaxf(acc[mt][nt][1] + bi1, 0.f);
                *(float2*)&g_h0[(size_t)r0 * HID + gcol] = v;
            }
            int r1 = r0 + 8;
            if (r1 < NN) {
                float2 v;
                v.x = fmaxf(acc[mt][nt][2] + bi0, 0.f);
                v.y = fmaxf(acc[mt][nt][3] + bi1, 0.f);
                *(float2*)&g_h0[(size_t)r1 * HID + gcol] = v;
            }
        }
    }
}

// ========== GEMM2: fp16 hi/lo A (exact) x fp16 W2, 2-pass; emits fp16 g_hops[0] ==========
__global__ void __launch_bounds__(256) k_gemm2_mma(const float* __restrict__ b2) {
    __shared__ __align__(16) uint32_t HsH[128 * 20];
    __shared__ __align__(16) uint32_t HsL[128 * 20];
    int tid  = threadIdx.x;
    int wid  = tid >> 5, lane = tid & 31;
    int wm0  = (wid >> 2) * 64;
    int nc   = wid & 3;
    int m0   = blockIdx.x * 128;

    float acc[4][2][4];
#pragma unroll
    for (int i = 0; i < 4; i++)
#pragma unroll
        for (int j = 0; j < 2; j++)
#pragma unroll
            for (int q = 0; q < 4; q++) acc[i][j][q] = 0.f;

    uint32_t asmH = smem_u32(HsH), asmL = smem_u32(HsL);
    uint32_t lrow = (uint32_t)(lane & 15) * 80u + (uint32_t)(lane >> 4) * 16u;
    int srow = tid >> 3, sseg = tid & 7;

    for (int ch = 0; ch < 8; ch++) {
        __syncthreads();
#pragma unroll
        for (int it = 0; it < 4; it++) {
            int row = srow + it * 32;
            int m = m0 + row;
            float4 v = make_float4(0.f, 0.f, 0.f, 0.f);
            if (m < NN) v = *(const float4*)&g_h0[(size_t)m * HID + ch * 32 + sseg * 4];
            int o = row * 20 + sseg * 2;
            float hx = __half2float(__float2half_rn(v.x));
            float hy = __half2float(__float2half_rn(v.y));
            float hz = __half2float(__float2half_rn(v.z));
            float hw = __half2float(__float2half_rn(v.w));
            HsH[o]     = pack_hf2(v.x, v.y);
            HsH[o + 1] = pack_hf2(v.z, v.w);
            HsL[o]     = pack_hf2(v.x - hx, v.y - hy);
            HsL[o + 1] = pack_hf2(v.z - hz, v.w - hw);
        }
        __syncthreads();
#pragma unroll
        for (int ks = 0; ks < 2; ks++) {
            uint32_t aH[4][4], aL[4][4];
#pragma unroll
            for (int mt = 0; mt < 4; mt++) {
                uint32_t off = (uint32_t)(wm0 + mt * 16) * 80u + (uint32_t)ks * 32u + lrow;
                LDSM4(aH[mt], asmH + off);
                LDSM4(aL[mt], asmL + off);
            }
            uint2 bF[2];
#pragma unroll
            for (int nt = 0; nt < 2; nt++) {
                int e0 = (ch * 2 + ks) * 8 + nc * 2 + nt;
                bF[nt] = g_W2frag[(size_t)e0 * 32 + lane];
            }
#pragma unroll
            for (int mt = 0; mt < 4; mt++)
#pragma unroll
                for (int nt = 0; nt < 2; nt++) {
                    mma16816hf(acc[mt][nt], aH[mt], bF[nt]);
                    mma16816hf(acc[mt][nt], aL[mt], bF[nt]);
                }
        }
    }

#pragma unroll
    for (int mt = 0; mt < 4; mt++) {
        int r0 = m0 + wm0 + mt * 16 + (lane >> 2);
#pragma unroll
        for (int nt = 0; nt < 2; nt++) {
            int gcol = nc * 16 + nt * 8 + (lane & 3) * 2;
            float bi0 = __ldg(&b2[gcol]), bi1 = __ldg(&b2[gcol + 1]);
#pragma unroll
            for (int h = 0; h < 2; h++) {
                int r = r0 + h * 8;
                if (r < NN) {
                    float vx = acc[mt][nt][h * 2 + 0] + bi0;
                    float vy = acc[mt][nt][h * 2 + 1] + bi1;
                    *(__half2*)&g_hops[0][(size_t)r * OUTC + gcol] = __floats2half2_rn(vx, vy);
                }
            }
        }
    }
}

// ===== SpMM hop: warp/node, simple loop (proven R14/R16 form), write-only hop output =====
__global__ void k_spmm(int hp) {
    int gid  = blockIdx.x * blockDim.x + threadIdx.x;
    int node = gid >> 5;
    int lane = gid & 31;
    if (node >= NN) return;
    const __half2* __restrict__ hin  = (const __half2*)g_hops[hp];
    __half2* __restrict__       hout = (__half2*)g_hops[hp + 1];

    int beg = g_colptr[node], end = g_colptr[node + 1];
    float a0 = 0.f, a1 = 0.f;
    for (int e = beg; e < end; e++) {
        int2 ed = g_edge[e];
        __half2 v = hin[(size_t)ed.x * 32 + lane];
        float w = __int_as_float(ed.y);
        float2 f = __half22float2(v);
        a0 = fmaf(w, f.x, a0);
        a1 = fmaf(w, f.y, a1);
    }
    // self loop
    {
        float d = g_dinv[node];
        float wd = d * d;
        __half2 v = hin[(size_t)node * 32 + lane];
        float2 f = __half22float2(v);
        a0 = fmaf(wd, f.x, a0);
        a1 = fmaf(wd, f.y, a1);
    }
    hout[(size_t)node * 32 + lane] = __floats2half2_rn(a0, a1);
}

// ===== final: hidden = sum_p coes[p]*h_p (fp32), then log_softmax =====
__global__ void k_lsm(const float* __restrict__ coes, float* __restrict__ out) {
    int gid  = blockIdx.x * blockDim.x + threadIdx.x;
    int node = gid >> 5;
    int lane = gid & 31;
    if (node >= NN) return;
    size_t ro = (size_t)node * 32 + lane;
    float2 acc = make_float2(0.f, 0.f);
#pragma unroll
    for (int p = 0; p <= PHOPS; p++) {
        float c = __ldg(&coes[p]);
        float2 f = __half22float2(((const __half2*)g_hops[p])[ro]);
        acc.x = fmaf(c, f.x, acc.x);
        acc.y = fmaf(c, f.y, acc.y);
    }
    float m = fmaxf(acc.x, acc.y);
#pragma unroll
    for (int off = 16; off; off >>= 1) m = fmaxf(m, __shfl_xor_sync(0xffffffffu, m, off));
    float s = expf(acc.x - m) + expf(acc.y - m);
#pragma unroll
    for (int off = 16; off; off >>= 1) s += __shfl_xor_sync(0xffffffffu, s, off);
    float l = m + logf(s);
    ((float2*)(out + (size_t)node * OUTC))[lane] = make_float2(acc.x - l, acc.y - l);
}

// ================= launch =================
extern "C" void kernel_launch(void* const* d_in, const int* in_sizes, int n_in,
                              void* d_out, int out_size) {
    const float* x    = (const float*)d_in[0];
    const void*  ei   = d_in[1];
    const float* W1   = (const float*)d_in[2];
    const float* b1   = (const float*)d_in[3];
    const float* W2   = (const float*)d_in[4];
    const float* b2   = (const float*)d_in[5];
    const float* coes = (const float*)d_in[6];
    (void)in_sizes; (void)n_in; (void)out_size;

    cudaFuncSetAttribute(k_gemm1_mma, cudaFuncAttributeMaxDynamicSharedMemorySize, G1_SMEM);

    // Fork-join: graph preprocessing on a side stream, MLP chain on the origin stream.
    cudaStream_t sp;
    cudaEvent_t e1, e2;
    cudaStreamCreateWithFlags(&sp, cudaStreamNonBlocking);
    cudaEventCreateWithFlags(&e1, cudaEventDisableTiming);
    cudaEventCreateWithFlags(&e2, cudaEventDisableTiming);

    cudaEventRecord(e1, 0);
    cudaStreamWaitEvent(sp, e1, 0);

    // --- side stream: edge preprocessing ---
    k_detect<<<1, 32, 0, sp>>>(ei);
    k_zero<<<(NN + 255) / 256, 256, 0, sp>>>();
    k_hist<<<(EE + 255) / 256, 256, 0, sp>>>(ei);
    k_dinv<<<(NN + 255) / 256, 256, 0, sp>>>();
    k_scan<<<1, 1024, 0, sp>>>();
    k_scatter<<<(EE + 255) / 256, 256, 0, sp>>>(ei);
    cudaEventRecord(e2, sp);

    // --- origin stream: MLP ---
    k_wprep<<<(1024 * 32 + 255) / 256, 256>>>(W1);
    k_w2prep<<<(128 * 32 + 255) / 256, 256>>>(W2);
    dim3 g1((NN + 127) / 128, 2);
    k_gemm1_mma<<<g1, 256, G1_SMEM>>>(x, b1);
    k_gemm2_mma<<<(NN + 127) / 128, 256>>>(b2);

    // join: SpMM needs CSR (side) + g_hops[0] (origin)
    cudaStreamWaitEvent(0, e2, 0);

    int warpsGrid = (NN * 32 + 255) / 256;
    for (int hp = 0; hp < PHOPS; hp++)
        k_spmm<<<warpsGrid, 256>>>(hp);

    k_lsm<<<warpsGrid, 256>>>(coes, (float*)d_out);

    cudaEventDestroy(e1);
    cudaEventDestroy(e2);
    cudaStreamDestroy(sp);
}